// round 1
// baseline (speedup 1.0000x reference)
#include <cuda_runtime.h>
#include <cstdint>

#define BATCH 65536

// ---------------- scratch (device globals; no allocation allowed) ----------
__device__ float g_h0[(size_t)BATCH * 1024];
__device__ float g_h1[(size_t)BATCH * 1024];
__device__ float g_h2[(size_t)BATCH * 512];
__device__ float g_s0[(size_t)BATCH * 256];
__device__ float g_s1[(size_t)BATCH * 128];
__device__ float g_w [(size_t)BATCH * 16];
__device__ float g_eh[(size_t)BATCH * 4096];   // experts hidden, [B, 16*256]

// ---------------- helpers ---------------------------------------------------
__device__ __forceinline__ float to_tf32(float x) {
    unsigned u;
    asm("cvt.rna.tf32.f32 %0, %1;" : "=r"(u) : "f"(x));
    return __uint_as_float(u);
}

__device__ __forceinline__ void mma_tf32(float* d, const float* a, const float* b) {
    asm volatile(
        "mma.sync.aligned.m16n8k8.row.col.f32.tf32.tf32.f32 "
        "{%0,%1,%2,%3}, {%4,%5,%6,%7}, {%8,%9}, {%0,%1,%2,%3};\n"
        : "+f"(d[0]), "+f"(d[1]), "+f"(d[2]), "+f"(d[3])
        : "r"(__float_as_uint(a[0])), "r"(__float_as_uint(a[1])),
          "r"(__float_as_uint(a[2])), "r"(__float_as_uint(a[3])),
          "r"(__float_as_uint(b[0])), "r"(__float_as_uint(b[1])));
}

#define BM 128
#define BN 128
#define BK 32
#define PAD 4

// ---------------- generic GEMM: C = act(A[M,K] @ B[K,N] + bias) -------------
// EXPERT: B is We1 [16, K, 256]; global col n maps to expert e=n>>8, col h=n&255.
template<bool RELU, bool EXPERT>
__global__ __launch_bounds__(256) void gemm_kernel(
    const float* __restrict__ A, const float* __restrict__ B,
    const float* __restrict__ bias, float* __restrict__ C,
    int K, int N)
{
    __shared__ float As[BM][BK + PAD];
    __shared__ float Bs[BK][BN + PAD];

    const int tid = threadIdx.x;
    const int m0 = blockIdx.y * BM;
    const int n0 = blockIdx.x * BN;

    const float* Bp;
    int ldb, bc0;
    if (EXPERT) {
        int e = n0 >> 8;
        Bp  = B + (size_t)e * K * 256;
        ldb = 256;
        bc0 = n0 & 255;
    } else {
        Bp  = B;
        ldb = N;
        bc0 = n0;
    }

    const int warp = tid >> 5, lane = tid & 31;
    const int rA = (warp >> 2) * 64;   // warpM * 64
    const int cB = (warp & 3) * 32;    // warpN * 32
    const int lg = lane >> 2, lt = lane & 3;

    float acc[4][4][4];
#pragma unroll
    for (int i = 0; i < 4; i++)
#pragma unroll
        for (int j = 0; j < 4; j++)
#pragma unroll
            for (int k = 0; k < 4; k++) acc[i][j][k] = 0.f;

    for (int k0 = 0; k0 < K; k0 += BK) {
        // A tile: 128x32 floats = 1024 float4, 4 per thread
#pragma unroll
        for (int j = 0; j < 4; j++) {
            int i = tid + j * 256;
            int r = i >> 3, c4 = (i & 7) << 2;
            float4 v = *(const float4*)(A + (size_t)(m0 + r) * K + k0 + c4);
            As[r][c4 + 0] = to_tf32(v.x); As[r][c4 + 1] = to_tf32(v.y);
            As[r][c4 + 2] = to_tf32(v.z); As[r][c4 + 3] = to_tf32(v.w);
        }
        // B tile: 32x128 floats = 1024 float4
#pragma unroll
        for (int j = 0; j < 4; j++) {
            int i = tid + j * 256;
            int r = i >> 5, c4 = (i & 31) << 2;
            float4 v = *(const float4*)(Bp + (size_t)(k0 + r) * ldb + bc0 + c4);
            Bs[r][c4 + 0] = to_tf32(v.x); Bs[r][c4 + 1] = to_tf32(v.y);
            Bs[r][c4 + 2] = to_tf32(v.z); Bs[r][c4 + 3] = to_tf32(v.w);
        }
        __syncthreads();

#pragma unroll
        for (int ks = 0; ks < 4; ks++) {
            const int kk = ks * 8;
            float a[4][4];
            float b[4][2];
#pragma unroll
            for (int mf = 0; mf < 4; mf++) {
                int r = rA + mf * 16 + lg;
                a[mf][0] = As[r][kk + lt];
                a[mf][1] = As[r + 8][kk + lt];
                a[mf][2] = As[r][kk + lt + 4];
                a[mf][3] = As[r + 8][kk + lt + 4];
            }
#pragma unroll
            for (int nf = 0; nf < 4; nf++) {
                int c = cB + nf * 8 + lg;
                b[nf][0] = Bs[kk + lt][c];
                b[nf][1] = Bs[kk + lt + 4][c];
            }
#pragma unroll
            for (int mf = 0; mf < 4; mf++)
#pragma unroll
                for (int nf = 0; nf < 4; nf++)
                    mma_tf32(acc[mf][nf], a[mf], b[nf]);
        }
        __syncthreads();
    }

    // epilogue: bias + optional relu
#pragma unroll
    for (int mf = 0; mf < 4; mf++) {
#pragma unroll
        for (int nf = 0; nf < 4; nf++) {
            int row = m0 + rA + mf * 16 + lg;
            int col = n0 + cB + nf * 8 + lt * 2;
            float b0 = bias[col], b1 = bias[col + 1];
            float v0 = acc[mf][nf][0] + b0, v1 = acc[mf][nf][1] + b1;
            float v2 = acc[mf][nf][2] + b0, v3 = acc[mf][nf][3] + b1;
            if (RELU) {
                v0 = fmaxf(v0, 0.f); v1 = fmaxf(v1, 0.f);
                v2 = fmaxf(v2, 0.f); v3 = fmaxf(v3, 0.f);
            }
            C[(size_t)row * N + col] = v0;
            C[(size_t)row * N + col + 1] = v1;
            C[(size_t)(row + 8) * N + col] = v2;
            C[(size_t)(row + 8) * N + col + 1] = v3;
        }
    }
}

// ---------------- selector logits + softmax (fp32 exact path) ---------------
// s1 [B,128] @ Ws2 [128,16] + bs2 -> softmax -> w [B,16]. One warp per row.
__global__ __launch_bounds__(256) void selector_kernel(
    const float* __restrict__ s1, const float* __restrict__ Ws2,
    const float* __restrict__ bs2, float* __restrict__ wout)
{
    __shared__ float Wsm[128 * 16];
    __shared__ float bsm[16];
    const int tid = threadIdx.x;
    for (int i = tid; i < 2048; i += 256) Wsm[i] = Ws2[i];
    if (tid < 16) bsm[tid] = bs2[tid];
    __syncthreads();

    const int warp = tid >> 5, lane = tid & 31;
    const int row = blockIdx.x * 8 + warp;

    float v[4];
#pragma unroll
    for (int j = 0; j < 4; j++) v[j] = s1[(size_t)row * 128 + j * 32 + lane];

    float mylog = -1e30f;
#pragma unroll
    for (int e = 0; e < 16; e++) {
        float p = 0.f;
#pragma unroll
        for (int j = 0; j < 4; j++) p += v[j] * Wsm[(j * 32 + lane) * 16 + e];
#pragma unroll
        for (int off = 16; off >= 1; off >>= 1)
            p += __shfl_xor_sync(0xffffffffu, p, off);
        if (lane == e) mylog = p + bsm[e];
    }
    // softmax across lanes 0..15 (width-16 groups)
    float m = mylog;
#pragma unroll
    for (int off = 8; off >= 1; off >>= 1)
        m = fmaxf(m, __shfl_xor_sync(0xffffffffu, m, off, 16));
    float ex = __expf(mylog - m);
    float s = ex;
#pragma unroll
    for (int off = 8; off >= 1; off >>= 1)
        s += __shfl_xor_sync(0xffffffffu, s, off, 16);
    if (lane < 16) wout[(size_t)row * 16 + lane] = ex / s;
}

// ---------------- expert layer 2 + weighted fusion --------------------------
// eh [B, 16*256] (relu already applied), We2 [16,256,32], be2 [16,32], w [B,16]
// out[b,a] = sum_e w[b,e] * (eh[b,e,:] @ We2[e] + be2[e])[a]
__global__ __launch_bounds__(256) void expert_fuse_kernel(
    const float* __restrict__ eh, const float* __restrict__ We2,
    const float* __restrict__ be2, const float* __restrict__ wsel,
    float* __restrict__ out)
{
    __shared__ float As[128][BK + PAD];
    __shared__ float Bs[BK][32 + PAD];
    __shared__ float wsm[128 * 16];

    const int tid = threadIdx.x;
    const int m0 = blockIdx.x * 128;
    const int warp = tid >> 5, lane = tid & 31;
    const int lg = lane >> 2, lt = lane & 3;

    for (int i = tid; i < 2048; i += 256) wsm[i] = wsel[(size_t)m0 * 16 + i];

    float accO[4][4];
#pragma unroll
    for (int nf = 0; nf < 4; nf++)
#pragma unroll
        for (int k = 0; k < 4; k++) accO[nf][k] = 0.f;

    for (int e = 0; e < 16; e++) {
        float accE[4][4];
#pragma unroll
        for (int nf = 0; nf < 4; nf++)
#pragma unroll
            for (int k = 0; k < 4; k++) accE[nf][k] = 0.f;

        for (int kt = 0; kt < 8; kt++) {
            __syncthreads();   // guard smem reuse (also orders wsm on first pass)
            // A tile: 128 rows x 32 cols from eh (col base e*256 + kt*32)
#pragma unroll
            for (int j = 0; j < 4; j++) {
                int i = tid + j * 256;
                int r = i >> 3, c4 = (i & 7) << 2;
                float4 v = *(const float4*)(eh + (size_t)(m0 + r) * 4096 + e * 256 + kt * 32 + c4);
                As[r][c4 + 0] = to_tf32(v.x); As[r][c4 + 1] = to_tf32(v.y);
                As[r][c4 + 2] = to_tf32(v.z); As[r][c4 + 3] = to_tf32(v.w);
            }
            // B tile: 32x32 from We2[e]
            {
                int r = tid >> 3, c4 = (tid & 7) << 2;
                float4 v = *(const float4*)(We2 + (size_t)e * 256 * 32 + (size_t)(kt * 32 + r) * 32 + c4);
                Bs[r][c4 + 0] = to_tf32(v.x); Bs[r][c4 + 1] = to_tf32(v.y);
                Bs[r][c4 + 2] = to_tf32(v.z); Bs[r][c4 + 3] = to_tf32(v.w);
            }
            __syncthreads();

#pragma unroll
            for (int ks = 0; ks < 4; ks++) {
                const int kk = ks * 8;
                float a[4];
                int r = warp * 16 + lg;
                a[0] = As[r][kk + lt];
                a[1] = As[r + 8][kk + lt];
                a[2] = As[r][kk + lt + 4];
                a[3] = As[r + 8][kk + lt + 4];
#pragma unroll
                for (int nf = 0; nf < 4; nf++) {
                    int c = nf * 8 + lg;
                    float b[2] = { Bs[kk + lt][c], Bs[kk + lt + 4][c] };
                    mma_tf32(accE[nf], a, b);
                }
            }
        }
        // weighted accumulation into output accumulator
        int r0 = warp * 16 + lg;
        float w0 = wsm[r0 * 16 + e];
        float w1 = wsm[(r0 + 8) * 16 + e];
#pragma unroll
        for (int nf = 0; nf < 4; nf++) {
            int col = nf * 8 + lt * 2;
            float b0 = be2[e * 32 + col], b1 = be2[e * 32 + col + 1];
            accO[nf][0] += w0 * (accE[nf][0] + b0);
            accO[nf][1] += w0 * (accE[nf][1] + b1);
            accO[nf][2] += w1 * (accE[nf][2] + b0);
            accO[nf][3] += w1 * (accE[nf][3] + b1);
        }
    }

    int r0 = m0 + warp * 16 + lg;
#pragma unroll
    for (int nf = 0; nf < 4; nf++) {
        int col = nf * 8 + lt * 2;
        out[(size_t)r0 * 32 + col]     = accO[nf][0];
        out[(size_t)r0 * 32 + col + 1] = accO[nf][1];
        out[(size_t)(r0 + 8) * 32 + col]     = accO[nf][2];
        out[(size_t)(r0 + 8) * 32 + col + 1] = accO[nf][3];
    }
}

// ---------------- launch -----------------------------------------------------
extern "C" void kernel_launch(void* const* d_in, const int* in_sizes, int n_in,
                              void* d_out, int out_size)
{
    const float* obs = (const float*)d_in[0];
    const float* Wb0 = (const float*)d_in[1];  const float* bb0 = (const float*)d_in[2];
    const float* Wb1 = (const float*)d_in[3];  const float* bb1 = (const float*)d_in[4];
    const float* Wb2 = (const float*)d_in[5];  const float* bb2 = (const float*)d_in[6];
    const float* We1 = (const float*)d_in[7];  const float* be1 = (const float*)d_in[8];
    const float* We2 = (const float*)d_in[9];  const float* be2 = (const float*)d_in[10];
    const float* Ws0 = (const float*)d_in[11]; const float* bs0 = (const float*)d_in[12];
    const float* Ws1 = (const float*)d_in[13]; const float* bs1 = (const float*)d_in[14];
    const float* Ws2 = (const float*)d_in[15]; const float* bs2 = (const float*)d_in[16];
    float* out = (float*)d_out;

    float *h0, *h1, *h2, *s0, *s1, *w, *eh;
    cudaGetSymbolAddress((void**)&h0, g_h0);
    cudaGetSymbolAddress((void**)&h1, g_h1);
    cudaGetSymbolAddress((void**)&h2, g_h2);
    cudaGetSymbolAddress((void**)&s0, g_s0);
    cudaGetSymbolAddress((void**)&s1, g_s1);
    cudaGetSymbolAddress((void**)&w,  g_w);
    cudaGetSymbolAddress((void**)&eh, g_eh);

    const dim3 blk(256);
    const int MB = BATCH / 128;   // 512 m-blocks

    // backbone
    gemm_kernel<true, false><<<dim3(1024 / 128, MB), blk>>>(obs, Wb0, bb0, h0, 512, 1024);
    gemm_kernel<true, false><<<dim3(1024 / 128, MB), blk>>>(h0, Wb1, bb1, h1, 1024, 1024);
    gemm_kernel<true, false><<<dim3(512 / 128, MB), blk>>>(h1, Wb2, bb2, h2, 1024, 512);
    // selector
    gemm_kernel<true, false><<<dim3(256 / 128, MB), blk>>>(obs, Ws0, bs0, s0, 512, 256);
    gemm_kernel<true, false><<<dim3(128 / 128, MB), blk>>>(s0, Ws1, bs1, s1, 256, 128);
    selector_kernel<<<BATCH / 8, blk>>>(s1, Ws2, bs2, w);
    // experts layer 1 (concatenated over experts): [B,512] @ [512, 16*256]
    gemm_kernel<true, true><<<dim3(4096 / 128, MB), blk>>>(h2, We1, be1, eh, 512, 4096);
    // experts layer 2 + softmax-weighted fusion
    expert_fuse_kernel<<<MB, blk>>>(eh, We2, be2, w, out);
}

// round 3
// speedup vs baseline: 1.7057x; 1.7057x over previous
#include <cuda_runtime.h>
#include <cstdint>

#define BATCH 65536

// ---------------- scratch (device globals; no allocation allowed) ----------
__device__ float g_h0[(size_t)BATCH * 1024];
__device__ float g_h1[(size_t)BATCH * 1024];
__device__ float g_h2[(size_t)BATCH * 512];
__device__ float g_s0[(size_t)BATCH * 256];
__device__ float g_s1[(size_t)BATCH * 128];
__device__ float g_w [(size_t)BATCH * 16];
__device__ float g_rb[(size_t)BATCH * 32];     // per-row fused bias: sum_e w*be2
__device__ float g_eh[(size_t)BATCH * 4096];   // w-scaled expert hidden [B, 16*256]

// ---------------- helpers ---------------------------------------------------
__device__ __forceinline__ float to_tf32(float x) {
    unsigned u;
    asm("cvt.rna.tf32.f32 %0, %1;" : "=r"(u) : "f"(x));
    return __uint_as_float(u);
}

__device__ __forceinline__ void mma_tf32(float* d, const float* a, const float* b) {
    asm volatile(
        "mma.sync.aligned.m16n8k8.row.col.f32.tf32.tf32.f32 "
        "{%0,%1,%2,%3}, {%4,%5,%6,%7}, {%8,%9}, {%0,%1,%2,%3};\n"
        : "+f"(d[0]), "+f"(d[1]), "+f"(d[2]), "+f"(d[3])
        : "r"(__float_as_uint(a[0])), "r"(__float_as_uint(a[1])),
          "r"(__float_as_uint(a[2])), "r"(__float_as_uint(a[3])),
          "r"(__float_as_uint(b[0])), "r"(__float_as_uint(b[1])));
}

#define BM 128
#define BN 128
#define BK 32
#define PAD 4

// ---------------- generic GEMM: C = act(A[M,K] @ B[K,N] + bias) -------------
// EXPERT: B is We1 [16, K, 256]; global col n maps to expert e=n>>8, col h=n&255.
// SCALE:  multiply post-relu output by wsel[row*16 + e] (requires EXPERT).
template<bool RELU, bool EXPERT, bool SCALE>
__global__ __launch_bounds__(256) void gemm_kernel(
    const float* __restrict__ A, const float* __restrict__ B,
    const float* __restrict__ bias, const float* __restrict__ wsel,
    float* __restrict__ C, int K, int N)
{
    __shared__ float As[BM][BK + PAD];
    __shared__ float Bs[BK][BN + PAD];

    const int tid = threadIdx.x;
    const int m0 = blockIdx.y * BM;
    const int n0 = blockIdx.x * BN;

    const float* Bp;
    int ldb, bc0;
    if (EXPERT) {
        int e = n0 >> 8;
        Bp  = B + (size_t)e * K * 256;
        ldb = 256;
        bc0 = n0 & 255;
    } else {
        Bp  = B;
        ldb = N;
        bc0 = n0;
    }
    const int eidx = EXPERT ? (n0 >> 8) : 0;

    const int warp = tid >> 5, lane = tid & 31;
    const int rA = (warp >> 2) * 64;   // warpM * 64
    const int cB = (warp & 3) * 32;    // warpN * 32
    const int lg = lane >> 2, lt = lane & 3;

    float acc[4][4][4];
#pragma unroll
    for (int i = 0; i < 4; i++)
#pragma unroll
        for (int j = 0; j < 4; j++)
#pragma unroll
            for (int k = 0; k < 4; k++) acc[i][j][k] = 0.f;

    for (int k0 = 0; k0 < K; k0 += BK) {
        // A tile: 128x32 floats = 1024 float4, 4 per thread
#pragma unroll
        for (int j = 0; j < 4; j++) {
            int i = tid + j * 256;
            int r = i >> 3, c4 = (i & 7) << 2;
            float4 v = *(const float4*)(A + (size_t)(m0 + r) * K + k0 + c4);
            As[r][c4 + 0] = to_tf32(v.x); As[r][c4 + 1] = to_tf32(v.y);
            As[r][c4 + 2] = to_tf32(v.z); As[r][c4 + 3] = to_tf32(v.w);
        }
        // B tile: 32x128 floats = 1024 float4
#pragma unroll
        for (int j = 0; j < 4; j++) {
            int i = tid + j * 256;
            int r = i >> 5, c4 = (i & 31) << 2;
            float4 v = *(const float4*)(Bp + (size_t)(k0 + r) * ldb + bc0 + c4);
            Bs[r][c4 + 0] = to_tf32(v.x); Bs[r][c4 + 1] = to_tf32(v.y);
            Bs[r][c4 + 2] = to_tf32(v.z); Bs[r][c4 + 3] = to_tf32(v.w);
        }
        __syncthreads();

#pragma unroll
        for (int ks = 0; ks < 4; ks++) {
            const int kk = ks * 8;
            float a[4][4];
            float b[4][2];
#pragma unroll
            for (int mf = 0; mf < 4; mf++) {
                int r = rA + mf * 16 + lg;
                a[mf][0] = As[r][kk + lt];
                a[mf][1] = As[r + 8][kk + lt];
                a[mf][2] = As[r][kk + lt + 4];
                a[mf][3] = As[r + 8][kk + lt + 4];
            }
#pragma unroll
            for (int nf = 0; nf < 4; nf++) {
                int c = cB + nf * 8 + lg;
                b[nf][0] = Bs[kk + lt][c];
                b[nf][1] = Bs[kk + lt + 4][c];
            }
#pragma unroll
            for (int mf = 0; mf < 4; mf++)
#pragma unroll
                for (int nf = 0; nf < 4; nf++)
                    mma_tf32(acc[mf][nf], a[mf], b[nf]);
        }
        __syncthreads();
    }

    // epilogue: bias + optional relu + optional per-row expert weight scale
#pragma unroll
    for (int mf = 0; mf < 4; mf++) {
        int row = m0 + rA + mf * 16 + lg;
        float ws0 = 1.f, ws1 = 1.f;
        if (SCALE) {
            ws0 = wsel[(size_t)row * 16 + eidx];
            ws1 = wsel[(size_t)(row + 8) * 16 + eidx];
        }
#pragma unroll
        for (int nf = 0; nf < 4; nf++) {
            int col = n0 + cB + nf * 8 + lt * 2;
            float b0 = bias[col], b1 = bias[col + 1];
            float v0 = acc[mf][nf][0] + b0, v1 = acc[mf][nf][1] + b1;
            float v2 = acc[mf][nf][2] + b0, v3 = acc[mf][nf][3] + b1;
            if (RELU) {
                v0 = fmaxf(v0, 0.f); v1 = fmaxf(v1, 0.f);
                v2 = fmaxf(v2, 0.f); v3 = fmaxf(v3, 0.f);
            }
            if (SCALE) {
                v0 *= ws0; v1 *= ws0;
                v2 *= ws1; v3 *= ws1;
            }
            C[(size_t)row * N + col] = v0;
            C[(size_t)row * N + col + 1] = v1;
            C[(size_t)(row + 8) * N + col] = v2;
            C[(size_t)(row + 8) * N + col + 1] = v3;
        }
    }
}

// ---------------- selector logits + softmax + fused row bias ----------------
// s1 [B,128] @ Ws2 [128,16] + bs2 -> softmax -> w [B,16]
// also rb[b,:] = sum_e w[b,e] * be2[e,:]   ([B,32])
__global__ __launch_bounds__(256) void selector_kernel(
    const float* __restrict__ s1, const float* __restrict__ Ws2,
    const float* __restrict__ bs2, const float* __restrict__ be2,
    float* __restrict__ wout, float* __restrict__ rbout)
{
    __shared__ float Wsm[128 * 16];
    __shared__ float bsm[16];
    __shared__ float be2s[16 * 32];
    const int tid = threadIdx.x;
    for (int i = tid; i < 2048; i += 256) Wsm[i] = Ws2[i];
    for (int i = tid; i < 512; i += 256) be2s[i] = be2[i];
    if (tid < 16) bsm[tid] = bs2[tid];
    __syncthreads();

    const int warp = tid >> 5, lane = tid & 31;
    const int row = blockIdx.x * 8 + warp;

    float v[4];
#pragma unroll
    for (int j = 0; j < 4; j++) v[j] = s1[(size_t)row * 128 + j * 32 + lane];

    float mylog = -1e30f;
#pragma unroll
    for (int e = 0; e < 16; e++) {
        float p = 0.f;
#pragma unroll
        for (int j = 0; j < 4; j++) p += v[j] * Wsm[(j * 32 + lane) * 16 + e];
#pragma unroll
        for (int off = 16; off >= 1; off >>= 1)
            p += __shfl_xor_sync(0xffffffffu, p, off);
        if (lane == e) mylog = p + bsm[e];
    }
    // softmax across lanes 0..15 (width-16 groups; lanes 16-31 hold garbage, unused)
    float m = mylog;
#pragma unroll
    for (int off = 8; off >= 1; off >>= 1)
        m = fmaxf(m, __shfl_xor_sync(0xffffffffu, m, off, 16));
    float ex = __expf(mylog - m);
    float s = ex;
#pragma unroll
    for (int off = 8; off >= 1; off >>= 1)
        s += __shfl_xor_sync(0xffffffffu, s, off, 16);
    float wv = ex / s;
    if (lane < 16) wout[(size_t)row * 16 + lane] = wv;

    // fused row bias: lane a (0..31) computes rb[row][a]
    float rbv = 0.f;
#pragma unroll
    for (int e = 0; e < 16; e++) {
        float we = __shfl_sync(0xffffffffu, wv, e);   // lanes 0..15 hold valid w
        rbv += we * be2s[e * 32 + lane];
    }
    rbout[(size_t)row * 32 + lane] = rbv;
}

// ---------------- final fused GEMM: out = g[B,4096] @ We2flat[4096,32] + rb --
// g already carries relu + w-scaling; We2 flat [k=e*256+h][a] row-major.
__global__ __launch_bounds__(256) void final_gemm(
    const float* __restrict__ g, const float* __restrict__ W2,
    const float* __restrict__ rb, float* __restrict__ out)
{
    __shared__ float As[128][BK + PAD];
    __shared__ float Bs[BK][32 + PAD];

    const int tid = threadIdx.x;
    const int m0 = blockIdx.x * 128;
    const int warp = tid >> 5, lane = tid & 31;   // 8 warps, warp tile m16 x n32
    const int lg = lane >> 2, lt = lane & 3;

    float acc[4][4];
#pragma unroll
    for (int nf = 0; nf < 4; nf++)
#pragma unroll
        for (int k = 0; k < 4; k++) acc[nf][k] = 0.f;

    for (int kt = 0; kt < 128; kt++) {
        const int k0 = kt * 32;
        __syncthreads();
        // A tile: 128x32 = 1024 float4, 4 per thread
#pragma unroll
        for (int j = 0; j < 4; j++) {
            int i = tid + j * 256;
            int r = i >> 3, c4 = (i & 7) << 2;
            float4 v = *(const float4*)(g + (size_t)(m0 + r) * 4096 + k0 + c4);
            As[r][c4 + 0] = to_tf32(v.x); As[r][c4 + 1] = to_tf32(v.y);
            As[r][c4 + 2] = to_tf32(v.z); As[r][c4 + 3] = to_tf32(v.w);
        }
        // B tile: 32x32 = 256 float4, 1 per thread
        {
            int r = tid >> 3, c4 = (tid & 7) << 2;
            float4 v = *(const float4*)(W2 + (size_t)(k0 + r) * 32 + c4);
            Bs[r][c4 + 0] = to_tf32(v.x); Bs[r][c4 + 1] = to_tf32(v.y);
            Bs[r][c4 + 2] = to_tf32(v.z); Bs[r][c4 + 3] = to_tf32(v.w);
        }
        __syncthreads();

#pragma unroll
        for (int ks = 0; ks < 4; ks++) {
            const int kk = ks * 8;
            float a[4];
            int r = warp * 16 + lg;
            a[0] = As[r][kk + lt];
            a[1] = As[r + 8][kk + lt];
            a[2] = As[r][kk + lt + 4];
            a[3] = As[r + 8][kk + lt + 4];
#pragma unroll
            for (int nf = 0; nf < 4; nf++) {
                int c = nf * 8 + lg;
                float b[2] = { Bs[kk + lt][c], Bs[kk + lt + 4][c] };
                mma_tf32(acc[nf], a, b);
            }
        }
    }

    // epilogue: + fused row bias, store
    int r0 = m0 + warp * 16 + lg;
#pragma unroll
    for (int nf = 0; nf < 4; nf++) {
        int col = nf * 8 + lt * 2;
        out[(size_t)r0 * 32 + col]     = acc[nf][0] + rb[(size_t)r0 * 32 + col];
        out[(size_t)r0 * 32 + col + 1] = acc[nf][1] + rb[(size_t)r0 * 32 + col + 1];
        out[(size_t)(r0 + 8) * 32 + col]     = acc[nf][2] + rb[(size_t)(r0 + 8) * 32 + col];
        out[(size_t)(r0 + 8) * 32 + col + 1] = acc[nf][3] + rb[(size_t)(r0 + 8) * 32 + col + 1];
    }
}

// ---------------- launch -----------------------------------------------------
extern "C" void kernel_launch(void* const* d_in, const int* in_sizes, int n_in,
                              void* d_out, int out_size)
{
    const float* obs = (const float*)d_in[0];
    const float* Wb0 = (const float*)d_in[1];  const float* bb0 = (const float*)d_in[2];
    const float* Wb1 = (const float*)d_in[3];  const float* bb1 = (const float*)d_in[4];
    const float* Wb2 = (const float*)d_in[5];  const float* bb2 = (const float*)d_in[6];
    const float* We1 = (const float*)d_in[7];  const float* be1 = (const float*)d_in[8];
    const float* We2 = (const float*)d_in[9];  const float* be2 = (const float*)d_in[10];
    const float* Ws0 = (const float*)d_in[11]; const float* bs0 = (const float*)d_in[12];
    const float* Ws1 = (const float*)d_in[13]; const float* bs1 = (const float*)d_in[14];
    const float* Ws2 = (const float*)d_in[15]; const float* bs2 = (const float*)d_in[16];
    float* out = (float*)d_out;

    float *h0, *h1, *h2, *s0, *s1, *w, *rb, *eh;
    cudaGetSymbolAddress((void**)&h0, g_h0);
    cudaGetSymbolAddress((void**)&h1, g_h1);
    cudaGetSymbolAddress((void**)&h2, g_h2);
    cudaGetSymbolAddress((void**)&s0, g_s0);
    cudaGetSymbolAddress((void**)&s1, g_s1);
    cudaGetSymbolAddress((void**)&w,  g_w);
    cudaGetSymbolAddress((void**)&rb, g_rb);
    cudaGetSymbolAddress((void**)&eh, g_eh);

    const dim3 blk(256);
    const int MB = BATCH / 128;   // 512 m-blocks

    // selector chain first (w needed by experts-L1 epilogue)
    gemm_kernel<true, false, false><<<dim3(2, MB), blk>>>(obs, Ws0, bs0, nullptr, s0, 512, 256);
    gemm_kernel<true, false, false><<<dim3(1, MB), blk>>>(s0, Ws1, bs1, nullptr, s1, 256, 128);
    selector_kernel<<<BATCH / 8, blk>>>(s1, Ws2, bs2, be2, w, rb);

    // backbone
    gemm_kernel<true, false, false><<<dim3(8, MB), blk>>>(obs, Wb0, bb0, nullptr, h0, 512, 1024);
    gemm_kernel<true, false, false><<<dim3(8, MB), blk>>>(h0, Wb1, bb1, nullptr, h1, 1024, 1024);
    gemm_kernel<true, false, false><<<dim3(4, MB), blk>>>(h1, Wb2, bb2, nullptr, h2, 1024, 512);

    // experts layer 1, w folded into epilogue: g = relu(h2 @ We1 + be1) * w
    gemm_kernel<true, true, true><<<dim3(32, MB), blk>>>(h2, We1, be1, w, eh, 512, 4096);

    // fusion as one GEMM: out = g @ We2flat + rb
    final_gemm<<<MB, blk>>>(eh, We2, rb, out);
}